// round 3
// baseline (speedup 1.0000x reference)
#include <cuda_runtime.h>

// out[i] = cos(x[i]) * cos(theta[i & 63])
// N = 33,554,432 fp32 -> 8,388,608 float4.
// Block owns 2048 consecutive float4 (8192 floats); each thread does 8 float4
// at stride 256. Per-thread stride = 1024 floats == 0 mod 64, so the theta
// vector is invariant across a thread's 8 iterations.

#define UNROLL 8
#define THREADS 256

__global__ void __launch_bounds__(THREADS) qab_kernel(
    const float4* __restrict__ x4,
    const float* __restrict__ theta,
    float4* __restrict__ out4,
    int nvec)
{
    __shared__ float ct[64];
    if (threadIdx.x < 64) {
        ct[threadIdx.x] = cosf(theta[threadIdx.x]);  // accurate; 64 values
    }
    __syncthreads();

    int base = blockIdx.x * (THREADS * UNROLL) + threadIdx.x;
    int t = (base << 2) & 63;                          // 16B-aligned theta slot
    float4 c = *reinterpret_cast<const float4*>(&ct[t]);

    if (base + (UNROLL - 1) * THREADS < nvec) {
        // Fast path: front-batch all 8 loads (MLP=8)
        float4 v[UNROLL];
        #pragma unroll
        for (int k = 0; k < UNROLL; k++)
            v[k] = x4[base + k * THREADS];

        #pragma unroll
        for (int k = 0; k < UNROLL; k++) {
            float4 r;
            r.x = __cosf(v[k].x) * c.x;
            r.y = __cosf(v[k].y) * c.y;
            r.z = __cosf(v[k].z) * c.z;
            r.w = __cosf(v[k].w) * c.w;
            __stcs(&out4[base + k * THREADS], r);      // streaming store
        }
    } else {
        // Tail path (unused for the shipped shape; kept for generality)
        #pragma unroll
        for (int k = 0; k < UNROLL; k++) {
            int i = base + k * THREADS;
            if (i < nvec) {
                float4 v = x4[i];
                float4 r;
                r.x = __cosf(v.x) * c.x;
                r.y = __cosf(v.y) * c.y;
                r.z = __cosf(v.z) * c.z;
                r.w = __cosf(v.w) * c.w;
                __stcs(&out4[i], r);
            }
        }
    }
}

extern "C" void kernel_launch(void* const* d_in, const int* in_sizes, int n_in,
                              void* d_out, int out_size)
{
    const float* x     = (const float*)d_in[0];
    const float* theta = (const float*)d_in[1];
    float* out         = (float*)d_out;

    int n    = out_size;     // total elements
    int nvec = n >> 2;       // float4 count

    int vec_per_block = THREADS * UNROLL;               // 2048 float4 / block
    int blocks = (nvec + vec_per_block - 1) / vec_per_block;

    qab_kernel<<<blocks, THREADS>>>(
        (const float4*)x, theta, (float4*)out, nvec);
}